// round 2
// baseline (speedup 1.0000x reference)
#include <cuda_runtime.h>
#include <cstdint>

// Problem constants (fixed by reference setup_inputs)
#define NB  8
#define LSZ 512
#define CC  6
#define NN  (NB * LSZ)       // 4096
#define KK  9
#define NK  (NN * KK)        // 36864

#define GL_PER   (2 * LSZ - 1)      // 1023 per graph (global edges)
#define SQ_PER   (2 * (LSZ - 2))    // 1020 per graph (sequential edges)
#define GL_TOT   (NB * GL_PER)      // 8184
#define SQ_TOT   (NB * SQ_PER)      // 8160
#define EDGE_TOT (2 * GL_TOT + 2 * SQ_TOT)   // 32688
#define PREP_BLOCKS (NN / 128)               // 32
#define EDGE_BLOCKS ((EDGE_TOT + 127) / 128) // 256

// SoA by channel: g_atoms[c*NN + node] = (x, y, z, wm)
// wm = |x|^2, or 1e30 sentinel if channel padded OR node is BOS/global.
__device__ float4 g_atoms[CC * NN];
__device__ int    g_info[NN];   // bits 0..5: pad mask; bit 6: BOS/global

typedef unsigned long long u64;

// ---- packed f32x2 helpers (each half rounds identically to scalar op) ----
__device__ __forceinline__ u64 pack2(float lo, float hi) {
    u64 r; asm("mov.b64 %0, {%1, %2};" : "=l"(r) : "f"(lo), "f"(hi)); return r;
}
__device__ __forceinline__ void unpack2(u64 v, float& lo, float& hi) {
    asm("mov.b64 {%0, %1}, %2;" : "=f"(lo), "=f"(hi) : "l"(v));
}
__device__ __forceinline__ u64 mul2(u64 a, u64 b) {
    u64 d; asm("mul.rn.f32x2 %0, %1, %2;" : "=l"(d) : "l"(a), "l"(b)); return d;
}
__device__ __forceinline__ u64 add2(u64 a, u64 b) {
    u64 d; asm("add.rn.f32x2 %0, %1, %2;" : "=l"(d) : "l"(a), "l"(b)); return d;
}
__device__ __forceinline__ u64 fma2(u64 a, u64 b, u64 c) {
    u64 d; asm("fma.rn.f32x2 %0, %1, %2, %3;" : "=l"(d) : "l"(a), "l"(b), "l"(c)); return d;
}

// ---------------------------------------------------------------------------
// Kernel 1: prep (SoA atoms + masks) merged with static edge lists
// ---------------------------------------------------------------------------
__global__ void __launch_bounds__(128)
prep_edges_kernel(const float* __restrict__ X,
                  const int* __restrict__ AP,
                  const int* __restrict__ S,
                  float* __restrict__ out) {
    const int tid = threadIdx.x;
    if (blockIdx.x < PREP_BLOCKS) {
        __shared__ float sX[128 * 18];
        const int base = blockIdx.x * 128;
#pragma unroll
        for (int kk = 0; kk < 18; kk++)
            sX[kk * 128 + tid] = X[base * 18 + kk * 128 + tid];
        __syncthreads();
        const int i = base + tid;
        const bool bos = (S[i] == 0);
        int mask = bos ? 64 : 0;
#pragma unroll
        for (int c = 0; c < CC; c++) {
            float x = sX[tid * 18 + c * 3 + 0];
            float y = sX[tid * 18 + c * 3 + 1];
            float z = sX[tid * 18 + c * 3 + 2];
            float sq = x * x + y * y + z * z;
            bool pad = (AP[i * CC + c] == 0);
            if (pad) mask |= (1 << c);
            float wm = (pad || bos) ? 1e30f : sq;
            g_atoms[c * NN + i] = make_float4(x, y, z, wm);
        }
        g_info[i] = mask;
    } else {
        const int t = (blockIdx.x - PREP_BLOCKS) * 128 + tid;
        if (t >= EDGE_TOT) return;
        int val;
        if (t < 2 * GL_TOT) {
            int r = t / GL_TOT, u = t % GL_TOT;
            int b = u / GL_PER, q = u % GL_PER;
            if (r == 0) val = (q < LSZ) ? 0 : (q - (LSZ - 1));
            else        val = (q < LSZ) ? q : 0;
            val += b * LSZ;
        } else {
            int t2 = t - 2 * GL_TOT;
            int r = t2 / SQ_TOT, u = t2 % SQ_TOT;
            int b = u / SQ_PER, q = u % SQ_PER;
            if (r == 0) val = (q < LSZ - 2) ? (q + 1) : (q - (LSZ - 2) + 2);
            else        val = (q < LSZ - 2) ? (q + 2) : (q - (LSZ - 2) + 1);
            val += b * LSZ;
        }
        out[4 * NK + t] = (float)val;
    }
}

// ---------------------------------------------------------------------------
// Kernel 2: per-row masked min-pair distance + exact top-9
// One CTA per row; 128 threads; thread t owns columns t, t+128, t+256, t+384
// processed as two f32x2-packed column pairs.
// ---------------------------------------------------------------------------
__global__ void __launch_bounds__(128)
knn_kernel(const int* __restrict__ sec, float* __restrict__ out) {
    const int i   = blockIdx.x;
    const int b   = i >> 9;
    const int tid = threadIdx.x;

    __shared__ u64 wOut[4 * KK];
    __shared__ u64 fin[KK];

    const int infoI = g_info[i];

    // BOS/global row: entire dist row is 1e10 -> dknn=1e10, valid=0, dst=-1.
    if (infoI & 64) {
        if (tid < KK) {
            out[0 * NK + i * KK + tid] = 1e10f;
            out[1 * NK + i * KK + tid] = (float)i;
            out[2 * NK + i * KK + tid] = -1.0f;
            out[3 * NK + i * KK + tid] = 0.0f;
        }
        return;
    }

    u64 loc[4];

    if ((infoI & 63) != 63) {
        // ---------------- fast path: row has >=1 valid channel ----------------
        u64 ax2[CC], ay2[CC], az2[CC], aw2[CC];
#pragma unroll
        for (int c = 0; c < CC; c++) {
            float4 A = g_atoms[c * NN + i];
            ax2[c] = pack2(A.x, A.x);
            ay2[c] = pack2(A.y, A.y);
            az2[c] = pack2(A.z, A.z);
            aw2[c] = pack2(A.w, A.w);
        }
        const u64 neg2 = pack2(-2.0f, -2.0f);

#pragma unroll
        for (int p = 0; p < 2; p++) {
            const int ja = (b << 9) + tid + (2 * p) * 128;
            const int jb = ja + 128;
            float mlo = 3.4e38f, mhi = 3.4e38f;
#pragma unroll
            for (int d = 0; d < CC; d++) {
                float4 Ba = g_atoms[d * NN + ja];
                float4 Bb = g_atoms[d * NN + jb];
                u64 bx2 = pack2(Ba.x, Bb.x);
                u64 by2 = pack2(Ba.y, Bb.y);
                u64 bz2 = pack2(Ba.z, Bb.z);
                u64 bw2 = pack2(Ba.w, Bb.w);
#pragma unroll
                for (int c = 0; c < CC; c++) {
                    // dot = fma(ax,bx, fma(ay,by, az*bz))  — bit-exact per half
                    u64 t2 = mul2(az2[c], bz2);
                    t2 = fma2(ay2[c], by2, t2);
                    t2 = fma2(ax2[c], bx2, t2);
                    // r = fma(-2, dot, Aw+Bw)              — bit-exact per half
                    u64 s2 = add2(aw2[c], bw2);
                    u64 r2 = fma2(neg2, t2, s2);
                    float rl, rh; unpack2(r2, rl, rh);
                    mlo = fminf(mlo, rl);
                    mhi = fminf(mhi, rh);
                }
            }
            // sqrt & clamp hoisted out of the 36-way min (monotone)
            float dl = sqrtf(fmaxf(mlo, 0.0f));
            float dh = sqrtf(fmaxf(mhi, 0.0f));
            loc[2 * p + 0] = ((u64)__float_as_uint(dl) << 32) | (unsigned)(tid + (2 * p) * 128);
            loc[2 * p + 1] = ((u64)__float_as_uint(dh) << 32) | (unsigned)(tid + (2 * p + 1) * 128);
        }
    } else {
        // ---------------- cold fallback: row has no valid channel -------------
        // dist_j = 1e10 (BOS col) or 1e10 + sqrt(min_all d2). valid=0 always,
        // so only approximate values matter (well within tolerance).
        float Ax[CC], Ay[CC], Az[CC], Asq[CC];
#pragma unroll
        for (int c = 0; c < CC; c++) {
            float4 A = g_atoms[c * NN + i];
            Ax[c] = A.x; Ay[c] = A.y; Az[c] = A.z;
            Asq[c] = A.x * A.x + A.y * A.y + A.z * A.z;
        }
#pragma unroll
        for (int t = 0; t < 4; t++) {
            const int jl = tid + t * 128;
            const int j  = (b << 9) + jl;
            float dist;
            if (g_info[j] & 64) {
                dist = 1e10f;
            } else {
                float m = 3.4e38f;
#pragma unroll
                for (int d = 0; d < CC; d++) {
                    float4 Bv = g_atoms[d * NN + j];
                    float bsq = Bv.x * Bv.x + Bv.y * Bv.y + Bv.z * Bv.z;
#pragma unroll
                    for (int c = 0; c < CC; c++) {
                        float dot = fmaf(Ax[c], Bv.x, fmaf(Ay[c], Bv.y, Az[c] * Bv.z));
                        float r = fmaf(-2.0f, dot, Asq[c] + bsq);
                        m = fminf(m, r);
                    }
                }
                dist = 1e10f + sqrtf(fmaxf(m, 0.0f));
            }
            loc[t] = ((u64)__float_as_uint(dist) << 32) | (unsigned)jl;
        }
    }

    // sort the 4 local keys ascending (network)
#define CSWAP(a_, b_) { if (loc[a_] > loc[b_]) { u64 t_ = loc[a_]; loc[a_] = loc[b_]; loc[b_] = t_; } }
    CSWAP(0, 1) CSWAP(2, 3) CSWAP(0, 2) CSWAP(1, 3) CSWAP(1, 2)
#undef CSWAP

    // per-warp: 9 rounds of argmin over the warp's 128 values
    const int wid  = tid >> 5;
    const int lane = tid & 31;
    int ptr = 0;
    for (int r = 0; r < KK; r++) {
        u64 key = (ptr < 4) ? loc[ptr] : 0xFFFFFFFFFFFFFFFFULL;
        u64 m = key;
#pragma unroll
        for (int o = 16; o > 0; o >>= 1) {
            u64 other = __shfl_xor_sync(0xFFFFFFFFu, m, o);
            m = min(m, other);
        }
        if (key == m) ptr++;    // keys unique (index in low bits) -> one winner
        if (lane == 0) wOut[wid * KK + r] = m;
    }
    __syncthreads();

    // merge 4 sorted 9-lists -> first 9
    if (tid == 0) {
        int p[4] = {0, 0, 0, 0};
        for (int r = 0; r < KK; r++) {
            u64 best = 0xFFFFFFFFFFFFFFFFULL;
            int bw = 0;
#pragma unroll
            for (int w = 0; w < 4; w++) {
                if (p[w] < KK) {
                    u64 v = wOut[w * KK + p[w]];
                    if (v < best) { best = v; bw = w; }
                }
            }
            p[bw]++;
            fin[r] = best;
        }
    }
    __syncthreads();

    if (tid < KK) {
        u64 v = fin[tid];
        float d  = __uint_as_float((unsigned)(v >> 32));
        int   jl = (int)(v & 0xFFFFFFFFu);
        int  dst = (b << 9) + jl;
        bool valid = (d < 1e10f) && (sec[i] == sec[dst]);
        out[0 * NK + i * KK + tid] = d;
        out[1 * NK + i * KK + tid] = (float)i;
        out[2 * NK + i * KK + tid] = valid ? (float)dst : -1.0f;
        out[3 * NK + i * KK + tid] = valid ? 1.0f : 0.0f;
    }
}

// ---------------------------------------------------------------------------
extern "C" void kernel_launch(void* const* d_in, const int* in_sizes, int n_in,
                              void* d_out, int out_size) {
    const float* X   = (const float*)d_in[0];
    const int*   AP  = (const int*)d_in[1];
    const int*   S   = (const int*)d_in[2];
    const int*   sec = (const int*)d_in[3];
    float* out = (float*)d_out;

    prep_edges_kernel<<<PREP_BLOCKS + EDGE_BLOCKS, 128>>>(X, AP, S, out);
    knn_kernel<<<NN, 128>>>(sec, out);
}

// round 3
// speedup vs baseline: 1.6898x; 1.6898x over previous
#include <cuda_runtime.h>
#include <cstdint>

// Problem constants (fixed by reference setup_inputs)
#define NB  8
#define LSZ 512
#define CC  6
#define NN  (NB * LSZ)       // 4096
#define KK  9
#define NK  (NN * KK)        // 36864
#define HB  256              // half graph (column pairing distance)

#define GL_PER   (2 * LSZ - 1)
#define SQ_PER   (2 * (LSZ - 2))
#define GL_TOT   (NB * GL_PER)      // 8184
#define SQ_TOT   (NB * SQ_PER)      // 8160
#define EDGE_TOT (2 * GL_TOT + 2 * SQ_TOT)   // 32688
#define EDGE_BLOCKS ((EDGE_TOT + 255) / 256) // 128

typedef unsigned long long u64;

// Paired SoA: element [c][b*256+q] = (val(node b*512+q), val(node b*512+q+256))
// pw holds |x|^2, or 1e30 sentinel if that channel is padded OR node is BOS.
__device__ float2 g_px[CC][NB * HB];
__device__ float2 g_py[CC][NB * HB];
__device__ float2 g_pz[CC][NB * HB];
__device__ float2 g_pw[CC][NB * HB];
__device__ int    g_info[NN];   // bits 0..5: pad mask; bit 6: BOS/global

// ---- packed f32x2 helpers (each half rounds identically to scalar op) ----
__device__ __forceinline__ u64 pack2(float lo, float hi) {
    u64 r; asm("mov.b64 %0, {%1, %2};" : "=l"(r) : "f"(lo), "f"(hi)); return r;
}
__device__ __forceinline__ void unpack2(u64 v, float& lo, float& hi) {
    asm("mov.b64 {%0, %1}, %2;" : "=f"(lo), "=f"(hi) : "l"(v));
}
__device__ __forceinline__ u64 mul2(u64 a, u64 b) {
    u64 d; asm("mul.rn.f32x2 %0, %1, %2;" : "=l"(d) : "l"(a), "l"(b)); return d;
}
__device__ __forceinline__ u64 add2(u64 a, u64 b) {
    u64 d; asm("add.rn.f32x2 %0, %1, %2;" : "=l"(d) : "l"(a), "l"(b)); return d;
}
__device__ __forceinline__ u64 fma2(u64 a, u64 b, u64 c) {
    u64 d; asm("fma.rn.f32x2 %0, %1, %2, %3;" : "=l"(d) : "l"(a), "l"(b), "l"(c)); return d;
}
__device__ __forceinline__ u64 ld2(const float2* p) {
    return *reinterpret_cast<const u64*>(p);   // lo bits = .x (column q), hi = .y (q+256)
}

// ---------------------------------------------------------------------------
// Kernel 1: prep (paired SoA + masks) merged with static edge lists
// blocks 0..7: one per graph, 256 threads (thread q handles nodes q, q+256)
// blocks 8.. : edge lists
// ---------------------------------------------------------------------------
__global__ void __launch_bounds__(256)
prep_edges_kernel(const float* __restrict__ X,
                  const int* __restrict__ AP,
                  const int* __restrict__ S,
                  float* __restrict__ out) {
    const int tid = threadIdx.x;
    if (blockIdx.x < NB) {
        const int b = blockIdx.x;
        const int q = tid;
        float ax[2][CC], ay[2][CC], az[2][CC], aw[2][CC];
#pragma unroll
        for (int h = 0; h < 2; h++) {
            const int i = b * LSZ + h * HB + q;
            const bool bos = (S[i] == 0);
            int mask = bos ? 64 : 0;
#pragma unroll
            for (int c = 0; c < CC; c++) {
                float x = X[(i * CC + c) * 3 + 0];
                float y = X[(i * CC + c) * 3 + 1];
                float z = X[(i * CC + c) * 3 + 2];
                float sq = x * x + y * y + z * z;
                bool pad = (AP[i * CC + c] == 0);
                if (pad) mask |= (1 << c);
                ax[h][c] = x; ay[h][c] = y; az[h][c] = z;
                aw[h][c] = (pad || bos) ? 1e30f : sq;
            }
            g_info[i] = mask;
        }
#pragma unroll
        for (int c = 0; c < CC; c++) {
            g_px[c][b * HB + q] = make_float2(ax[0][c], ax[1][c]);
            g_py[c][b * HB + q] = make_float2(ay[0][c], ay[1][c]);
            g_pz[c][b * HB + q] = make_float2(az[0][c], az[1][c]);
            g_pw[c][b * HB + q] = make_float2(aw[0][c], aw[1][c]);
        }
    } else {
        const int t = (blockIdx.x - NB) * 256 + tid;
        if (t >= EDGE_TOT) return;
        int val;
        if (t < 2 * GL_TOT) {
            int r = t / GL_TOT, u = t % GL_TOT;
            int b = u / GL_PER, q = u % GL_PER;
            if (r == 0) val = (q < LSZ) ? 0 : (q - (LSZ - 1));
            else        val = (q < LSZ) ? q : 0;
            val += b * LSZ;
        } else {
            int t2 = t - 2 * GL_TOT;
            int r = t2 / SQ_TOT, u = t2 % SQ_TOT;
            int b = u / SQ_PER, q = u % SQ_PER;
            if (r == 0) val = (q < LSZ - 2) ? (q + 1) : (q - (LSZ - 2) + 2);
            else        val = (q < LSZ - 2) ? (q + 2) : (q - (LSZ - 2) + 1);
            val += b * LSZ;
        }
        out[4 * NK + t] = (float)val;
    }
}

// ---------------------------------------------------------------------------
// Kernel 2: per-row masked min-pair distance + exact top-9
// One CTA per row; 128 threads; thread t owns column pairs q=t (cols t,t+256)
// and q=t+128 (cols t+128,t+384), each pair processed in packed f32x2.
// ---------------------------------------------------------------------------
__global__ void __launch_bounds__(128)
knn_kernel(const int* __restrict__ sec, float* __restrict__ out) {
    const int i   = blockIdx.x;
    const int b   = i >> 9;
    const int tid = threadIdx.x;

    __shared__ u64 wOut[4 * KK];
    __shared__ u64 fin[KK];

    const int infoI = g_info[i];

    // BOS/global row: entire dist row is 1e10 -> dknn=1e10, valid=0, dst=-1.
    if (infoI & 64) {
        if (tid < KK) {
            out[0 * NK + i * KK + tid] = 1e10f;
            out[1 * NK + i * KK + tid] = (float)i;
            out[2 * NK + i * KK + tid] = -1.0f;
            out[3 * NK + i * KK + tid] = 0.0f;
        }
        return;
    }

    const int base = b * HB;
    const int li   = i & (LSZ - 1);
    const int qi   = li & (HB - 1);
    const int hi_  = li >> 8;       // which half of the pair holds row i

    u64 loc[4];

    if ((infoI & 63) != 63) {
        // ---------------- fast path: row has >=1 valid channel ----------------
        u64 ax2[CC], ay2[CC], az2[CC], aw2[CC];
#pragma unroll
        for (int c = 0; c < CC; c++) {
            float2 vx = g_px[c][base + qi];
            float2 vy = g_py[c][base + qi];
            float2 vz = g_pz[c][base + qi];
            float2 vw = g_pw[c][base + qi];
            float x = hi_ ? vx.y : vx.x;
            float y = hi_ ? vy.y : vy.x;
            float z = hi_ ? vz.y : vz.x;
            float w = hi_ ? vw.y : vw.x;
            ax2[c] = pack2(x, x);
            ay2[c] = pack2(y, y);
            az2[c] = pack2(z, z);
            aw2[c] = pack2(w, w);
        }
        const u64 neg2 = pack2(-2.0f, -2.0f);

#pragma unroll
        for (int p = 0; p < 2; p++) {
            const int q = tid + p * 128;
            float mlo = 3.4e38f, mhi = 3.4e38f;
#pragma unroll
            for (int d = 0; d < CC; d++) {
                u64 bx2 = ld2(&g_px[d][base + q]);
                u64 by2 = ld2(&g_py[d][base + q]);
                u64 bz2 = ld2(&g_pz[d][base + q]);
                u64 bw2 = ld2(&g_pw[d][base + q]);
#pragma unroll
                for (int c = 0; c < CC; c++) {
                    // dot = fma(ax,bx, fma(ay,by, az*bz))  — bit-exact per half
                    u64 t2 = mul2(az2[c], bz2);
                    t2 = fma2(ay2[c], by2, t2);
                    t2 = fma2(ax2[c], bx2, t2);
                    // r = fma(-2, dot, Aw+Bw)              — bit-exact per half
                    u64 s2 = add2(aw2[c], bw2);
                    u64 r2 = fma2(neg2, t2, s2);
                    float rl, rh; unpack2(r2, rl, rh);   // free (register pair)
                    mlo = fminf(mlo, rl);
                    mhi = fminf(mhi, rh);
                }
            }
            // sqrt & clamp hoisted out of the 36-way min (monotone)
            float dl = sqrtf(fmaxf(mlo, 0.0f));
            float dh = sqrtf(fmaxf(mhi, 0.0f));
            loc[2 * p + 0] = ((u64)__float_as_uint(dl) << 32) | (unsigned)q;
            loc[2 * p + 1] = ((u64)__float_as_uint(dh) << 32) | (unsigned)(q + HB);
        }
    } else {
        // ---------------- cold fallback: row has no valid channel -------------
        // dist_j = 1e10 (BOS col) or 1e10 + sqrt(min_all d2); valid=0 always.
        float Ax[CC], Ay[CC], Az[CC], Asq[CC];
#pragma unroll
        for (int c = 0; c < CC; c++) {
            float2 vx = g_px[c][base + qi];
            float2 vy = g_py[c][base + qi];
            float2 vz = g_pz[c][base + qi];
            float x = hi_ ? vx.y : vx.x;
            float y = hi_ ? vy.y : vy.x;
            float z = hi_ ? vz.y : vz.x;
            Ax[c] = x; Ay[c] = y; Az[c] = z;
            Asq[c] = x * x + y * y + z * z;
        }
#pragma unroll
        for (int t = 0; t < 4; t++) {
            const int jl = tid + t * 128;
            const int q  = jl & (HB - 1);
            const int hh = jl >> 8;
            const int j  = (b << 9) + jl;
            float dist;
            if (g_info[j] & 64) {
                dist = 1e10f;
            } else {
                float m = 3.4e38f;
#pragma unroll
                for (int d = 0; d < CC; d++) {
                    float2 vx = g_px[d][base + q];
                    float2 vy = g_py[d][base + q];
                    float2 vz = g_pz[d][base + q];
                    float bx = hh ? vx.y : vx.x;
                    float by = hh ? vy.y : vy.x;
                    float bz = hh ? vz.y : vz.x;
                    float bsq = bx * bx + by * by + bz * bz;
#pragma unroll
                    for (int c = 0; c < CC; c++) {
                        float dot = fmaf(Ax[c], bx, fmaf(Ay[c], by, Az[c] * bz));
                        float r = fmaf(-2.0f, dot, Asq[c] + bsq);
                        m = fminf(m, r);
                    }
                }
                dist = 1e10f + sqrtf(fmaxf(m, 0.0f));
            }
            loc[t] = ((u64)__float_as_uint(dist) << 32) | (unsigned)jl;
        }
    }

    // sort the 4 local keys ascending (network)
#define CSWAP(a_, b_) { if (loc[a_] > loc[b_]) { u64 t_ = loc[a_]; loc[a_] = loc[b_]; loc[b_] = t_; } }
    CSWAP(0, 1) CSWAP(2, 3) CSWAP(0, 2) CSWAP(1, 3) CSWAP(1, 2)
#undef CSWAP

    // per-warp: 9 rounds of argmin over the warp's 128 values
    const int wid  = tid >> 5;
    const int lane = tid & 31;
    int ptr = 0;
    for (int r = 0; r < KK; r++) {
        u64 key = (ptr < 4) ? loc[ptr] : 0xFFFFFFFFFFFFFFFFULL;
        u64 m = key;
#pragma unroll
        for (int o = 16; o > 0; o >>= 1) {
            u64 other = __shfl_xor_sync(0xFFFFFFFFu, m, o);
            m = min(m, other);
        }
        if (key == m) ptr++;    // keys unique (index in low bits) -> one winner
        if (lane == 0) wOut[wid * KK + r] = m;
    }
    __syncthreads();

    // merge 4 sorted 9-lists -> first 9
    if (tid == 0) {
        int p[4] = {0, 0, 0, 0};
        for (int r = 0; r < KK; r++) {
            u64 best = 0xFFFFFFFFFFFFFFFFULL;
            int bw = 0;
#pragma unroll
            for (int w = 0; w < 4; w++) {
                if (p[w] < KK) {
                    u64 v = wOut[w * KK + p[w]];
                    if (v < best) { best = v; bw = w; }
                }
            }
            p[bw]++;
            fin[r] = best;
        }
    }
    __syncthreads();

    if (tid < KK) {
        u64 v = fin[tid];
        float d  = __uint_as_float((unsigned)(v >> 32));
        int   jl = (int)(v & 0xFFFFFFFFu);
        int  dst = (b << 9) + jl;
        bool valid = (d < 1e10f) && (sec[i] == sec[dst]);
        out[0 * NK + i * KK + tid] = d;
        out[1 * NK + i * KK + tid] = (float)i;
        out[2 * NK + i * KK + tid] = valid ? (float)dst : -1.0f;
        out[3 * NK + i * KK + tid] = valid ? 1.0f : 0.0f;
    }
}

// ---------------------------------------------------------------------------
extern "C" void kernel_launch(void* const* d_in, const int* in_sizes, int n_in,
                              void* d_out, int out_size) {
    const float* X   = (const float*)d_in[0];
    const int*   AP  = (const int*)d_in[1];
    const int*   S   = (const int*)d_in[2];
    const int*   sec = (const int*)d_in[3];
    float* out = (float*)d_out;

    prep_edges_kernel<<<NB + EDGE_BLOCKS, 256>>>(X, AP, S, out);
    knn_kernel<<<NN, 128>>>(sec, out);
}

// round 5
// speedup vs baseline: 1.8966x; 1.1224x over previous
#include <cuda_runtime.h>
#include <cstdint>

// Problem constants (fixed by reference setup_inputs)
#define NB  8
#define LSZ 512
#define CC  6
#define NN  (NB * LSZ)       // 4096
#define KK  9
#define NK  (NN * KK)        // 36864
#define HB  256              // half graph (column pairing distance)

#define GL_PER   (2 * LSZ - 1)
#define SQ_PER   (2 * (LSZ - 2))
#define GL_TOT   (NB * GL_PER)      // 8184
#define SQ_TOT   (NB * SQ_PER)      // 8160
#define EDGE_TOT (2 * GL_TOT + 2 * SQ_TOT)   // 32688
#define EDGE_BLOCKS ((EDGE_TOT + 255) / 256) // 128

typedef unsigned long long u64;

// Interleaved paired SoA per channel c, per (graph b, q in [0,256)):
//   g_q1[c][b*HB+q] = (x_lo, x_hi, y_lo, y_hi)
//   g_q2[c][b*HB+q] = (z_lo, z_hi, w_lo, w_hi)
// lo = node b*512+q, hi = node b*512+q+256.
// w = |x|^2, or 1e30 sentinel if channel padded OR node is BOS/global.
__device__ float4 g_q1[CC][NB * HB];
__device__ float4 g_q2[CC][NB * HB];
__device__ int    g_info[NN];   // bits 0..5: pad mask; bit 6: BOS/global

// ---- packed f32x2 helpers (each half rounds identically to scalar op) ----
__device__ __forceinline__ u64 pack2(float lo, float hi) {
    u64 r; asm("mov.b64 %0, {%1, %2};" : "=l"(r) : "f"(lo), "f"(hi)); return r;
}
__device__ __forceinline__ void unpack2(u64 v, float& lo, float& hi) {
    asm("mov.b64 {%0, %1}, %2;" : "=f"(lo), "=f"(hi) : "l"(v));
}
__device__ __forceinline__ u64 mul2(u64 a, u64 b) {
    u64 d; asm("mul.rn.f32x2 %0, %1, %2;" : "=l"(d) : "l"(a), "l"(b)); return d;
}
__device__ __forceinline__ u64 add2(u64 a, u64 b) {
    u64 d; asm("add.rn.f32x2 %0, %1, %2;" : "=l"(d) : "l"(a), "l"(b)); return d;
}
__device__ __forceinline__ u64 fma2(u64 a, u64 b, u64 c) {
    u64 d; asm("fma.rn.f32x2 %0, %1, %2, %3;" : "=l"(d) : "l"(a), "l"(b), "l"(c)); return d;
}

// ---------------------------------------------------------------------------
// Kernel 1: prep (interleaved paired SoA + masks) merged with edge lists
// ---------------------------------------------------------------------------
__global__ void __launch_bounds__(256)
prep_edges_kernel(const float* __restrict__ X,
                  const int* __restrict__ AP,
                  const int* __restrict__ S,
                  float* __restrict__ out) {
    const int tid = threadIdx.x;
    if (blockIdx.x < NB) {
        const int b = blockIdx.x;
        const int q = tid;
        float ax[2][CC], ay[2][CC], az[2][CC], aw[2][CC];
#pragma unroll
        for (int h = 0; h < 2; h++) {
            const int i = b * LSZ + h * HB + q;
            const bool bos = (S[i] == 0);
            int mask = bos ? 64 : 0;
#pragma unroll
            for (int c = 0; c < CC; c++) {
                float x = X[(i * CC + c) * 3 + 0];
                float y = X[(i * CC + c) * 3 + 1];
                float z = X[(i * CC + c) * 3 + 2];
                float sq = x * x + y * y + z * z;
                bool pad = (AP[i * CC + c] == 0);
                if (pad) mask |= (1 << c);
                ax[h][c] = x; ay[h][c] = y; az[h][c] = z;
                aw[h][c] = (pad || bos) ? 1e30f : sq;
            }
            g_info[i] = mask;
        }
#pragma unroll
        for (int c = 0; c < CC; c++) {
            g_q1[c][b * HB + q] = make_float4(ax[0][c], ax[1][c], ay[0][c], ay[1][c]);
            g_q2[c][b * HB + q] = make_float4(az[0][c], az[1][c], aw[0][c], aw[1][c]);
        }
    } else {
        const int t = (blockIdx.x - NB) * 256 + tid;
        if (t >= EDGE_TOT) return;
        int val;
        if (t < 2 * GL_TOT) {
            int r = t / GL_TOT, u = t % GL_TOT;
            int b = u / GL_PER, q = u % GL_PER;
            if (r == 0) val = (q < LSZ) ? 0 : (q - (LSZ - 1));
            else        val = (q < LSZ) ? q : 0;
            val += b * LSZ;
        } else {
            int t2 = t - 2 * GL_TOT;
            int r = t2 / SQ_TOT, u = t2 % SQ_TOT;
            int b = u / SQ_PER, q = u % SQ_PER;
            if (r == 0) val = (q < LSZ - 2) ? (q + 1) : (q - (LSZ - 2) + 2);
            else        val = (q < LSZ - 2) ? (q + 2) : (q - (LSZ - 2) + 1);
            val += b * LSZ;
        }
        out[4 * NK + t] = (float)val;
    }
}

// ---------------------------------------------------------------------------
// Kernel 2: per-row masked min-pair distance (bit-exact) + top-9 with exact
// lower-index tie-break. One CTA per row; 128 threads; thread t owns columns
// t, t+128, t+256, t+384 (kept ascending for stable tie order), computed as
// two packed f32x2 column pairs (t,t+256) and (t+128,t+384).
// ---------------------------------------------------------------------------
__global__ void __launch_bounds__(128)
knn_kernel(const int* __restrict__ sec, float* __restrict__ out) {
    const int i   = blockIdx.x;
    const int b   = i >> 9;
    const int tid = threadIdx.x;
    const float INF = __int_as_float(0x7f800000);

    __shared__ u64 wOut[4 * KK];

    const int infoI = g_info[i];

    // BOS/global row: entire dist row is 1e10 -> dknn=1e10, valid=0, dst=-1.
    if (infoI & 64) {
        if (tid < KK) {
            out[0 * NK + i * KK + tid] = 1e10f;
            out[1 * NK + i * KK + tid] = (float)i;
            out[2 * NK + i * KK + tid] = -1.0f;
            out[3 * NK + i * KK + tid] = 0.0f;
        }
        return;
    }

    const int base = b * HB;
    const int li   = i & (LSZ - 1);
    const int qi   = li & (HB - 1);
    const int hi_  = li >> 8;       // which half of the pair holds row i

    // per-thread candidates in ascending column order
    float d0, d1, d2, d3;
    int   jl0 = tid, jl1 = tid + 128, jl2 = tid + 256, jl3 = tid + 384;

    if ((infoI & 63) != 63) {
        // ---------------- fast path: row has >=1 valid channel ----------------
        u64 ax2[CC], ay2[CC], az2[CC], aw2[CC];
#pragma unroll
        for (int c = 0; c < CC; c++) {
            float4 q1 = g_q1[c][base + qi];
            float4 q2 = g_q2[c][base + qi];
            float x = hi_ ? q1.y : q1.x;
            float y = hi_ ? q1.w : q1.z;
            float z = hi_ ? q2.y : q2.x;
            float w = hi_ ? q2.w : q2.z;
            ax2[c] = pack2(x, x);
            ay2[c] = pack2(y, y);
            az2[c] = pack2(z, z);
            aw2[c] = pack2(w, w);
        }
        const u64 neg2 = pack2(-2.0f, -2.0f);

#pragma unroll
        for (int p = 0; p < 2; p++) {
            const int q = tid + p * 128;
            float mlo = 3.4e38f, mhi = 3.4e38f;
#pragma unroll
            for (int d = 0; d < CC; d++) {
                ulonglong2 vA = *reinterpret_cast<const ulonglong2*>(&g_q1[d][base + q]);
                ulonglong2 vB = *reinterpret_cast<const ulonglong2*>(&g_q2[d][base + q]);
                const u64 bx2 = vA.x, by2 = vA.y, bz2 = vB.x, bw2 = vB.y;
#pragma unroll
                for (int c = 0; c < CC; c++) {
                    // BIT-EXACT chain (validated): dot = fma(ax,bx,fma(ay,by,az*bz));
                    // r = fma(-2, dot, aw+bw)
                    u64 t2 = mul2(az2[c], bz2);
                    t2 = fma2(ay2[c], by2, t2);
                    t2 = fma2(ax2[c], bx2, t2);
                    u64 s2 = add2(aw2[c], bw2);
                    u64 r2 = fma2(neg2, t2, s2);
                    float rl, rh; unpack2(r2, rl, rh);
                    mlo = fminf(mlo, rl);
                    mhi = fminf(mhi, rh);
                }
            }
            // sqrt & clamp hoisted out of the 36-way min (monotone)
            float dl = sqrtf(fmaxf(mlo, 0.0f));
            float dh = sqrtf(fmaxf(mhi, 0.0f));
            if (p == 0) { d0 = dl; d2 = dh; }   // cols tid, tid+256
            else        { d1 = dl; d3 = dh; }   // cols tid+128, tid+384
        }
    } else {
        // ---------------- cold fallback: row has no valid channel -------------
        // dist_j = 1e10 (BOS col) or 1e10 + sqrt(min_all d2); valid=0 always.
        float Ax[CC], Ay[CC], Az[CC], Asq[CC];
#pragma unroll
        for (int c = 0; c < CC; c++) {
            float4 q1 = g_q1[c][base + qi];
            float4 q2 = g_q2[c][base + qi];
            float x = hi_ ? q1.y : q1.x;
            float y = hi_ ? q1.w : q1.z;
            float z = hi_ ? q2.y : q2.x;
            Ax[c] = x; Ay[c] = y; Az[c] = z;
            Asq[c] = x * x + y * y + z * z;
        }
        float dv[4];
#pragma unroll
        for (int t = 0; t < 4; t++) {
            const int jl = tid + t * 128;          // ascending, matches jl0..jl3
            const int q  = jl & (HB - 1);
            const int hh = jl >> 8;
            const int j  = (b << 9) + jl;
            float dist;
            if (g_info[j] & 64) {
                dist = 1e10f;
            } else {
                float m = 3.4e38f;
#pragma unroll
                for (int d = 0; d < CC; d++) {
                    float4 q1 = g_q1[d][base + q];
                    float4 q2 = g_q2[d][base + q];
                    float bx = hh ? q1.y : q1.x;
                    float by = hh ? q1.w : q1.z;
                    float bz = hh ? q2.y : q2.x;
                    float bsq = bx * bx + by * by + bz * bz;
#pragma unroll
                    for (int c = 0; c < CC; c++) {
                        float dot = fmaf(Ax[c], bx, fmaf(Ay[c], by, Az[c] * bz));
                        float r = fmaf(-2.0f, dot, Asq[c] + bsq);
                        m = fminf(m, r);
                    }
                }
                dist = 1e10f + sqrtf(fmaxf(m, 0.0f));
            }
            dv[t] = dist;
        }
        d0 = dv[0]; d1 = dv[1]; d2 = dv[2]; d3 = dv[3];
    }

    // stable sort of 4 (dist, jl) candidates (strict >; equal keys never cross,
    // so ties stay in ascending-jl order)
#define CSWAP(da, db, ja, jb) { \
    if (da > db) { float tf = da; da = db; db = tf; int ti = ja; ja = jb; jb = ti; } }
    CSWAP(d0, d1, jl0, jl1) CSWAP(d2, d3, jl2, jl3)
    CSWAP(d0, d2, jl0, jl2) CSWAP(d1, d3, jl1, jl3)
    CSWAP(d1, d2, jl1, jl2)
#undef CSWAP

    // per-warp: 9 rounds of f32 warp-min with exact lower-index tie-break
    const int wid = tid >> 5;
    for (int r = 0; r < KK; r++) {
        float m = d0;
#pragma unroll
        for (int o = 16; o > 0; o >>= 1)
            m = fminf(m, __shfl_xor_sync(0xFFFFFFFFu, m, o));
        int cj = (d0 == m) ? jl0 : 0x7FFFFFFF;   // tie-break: min column index
#pragma unroll
        for (int o = 16; o > 0; o >>= 1)
            cj = min(cj, __shfl_xor_sync(0xFFFFFFFFu, cj, o));
        if (jl0 == cj) {                          // unique owner (jl unique)
            wOut[wid * KK + r] = ((u64)__float_as_uint(m) << 32) | (unsigned)cj;
            // pop head (shift register; no dynamic indexing)
            d0 = d1; jl0 = jl1;
            d1 = d2; jl1 = jl2;
            d2 = d3; jl2 = jl3;
            d3 = INF;
        }
    }
    __syncthreads();

    // parallel rank-merge of 4 sorted 9-lists; ranks < 9 write outputs directly.
    // u64 keys carry (dist_bits, jl) so cross-warp ties also rank by lower jl.
    if (tid < 4 * KK) {
        const u64 key = wOut[tid];
        const int myw = tid / KK;
        int rank = tid - myw * KK;
#pragma unroll
        for (int w = 0; w < 4; w++) {
            if (w == myw) continue;
#pragma unroll
            for (int rr = 0; rr < KK; rr++)
                rank += (wOut[w * KK + rr] < key);
        }
        if (rank < KK) {
            float dd = __uint_as_float((unsigned)(key >> 32));
            int   jl = (int)(key & 0xFFFFFFFFu);
            int  dst = (b << 9) + jl;
            bool valid = (dd < 1e10f) && (sec[i] == sec[dst]);
            out[0 * NK + i * KK + rank] = dd;
            out[1 * NK + i * KK + rank] = (float)i;
            out[2 * NK + i * KK + rank] = valid ? (float)dst : -1.0f;
            out[3 * NK + i * KK + rank] = valid ? 1.0f : 0.0f;
        }
    }
}

// ---------------------------------------------------------------------------
extern "C" void kernel_launch(void* const* d_in, const int* in_sizes, int n_in,
                              void* d_out, int out_size) {
    const float* X   = (const float*)d_in[0];
    const int*   AP  = (const int*)d_in[1];
    const int*   S   = (const int*)d_in[2];
    const int*   sec = (const int*)d_in[3];
    float* out = (float*)d_out;

    prep_edges_kernel<<<NB + EDGE_BLOCKS, 256>>>(X, AP, S, out);
    knn_kernel<<<NN, 128>>>(sec, out);
}

// round 6
// speedup vs baseline: 2.1724x; 1.1454x over previous
#include <cuda_runtime.h>
#include <cstdint>

// Problem constants (fixed by reference setup_inputs)
#define NB  8
#define LSZ 512
#define CC  6
#define NN  (NB * LSZ)       // 4096
#define KK  9
#define NK  (NN * KK)        // 36864
#define HB  256              // half graph (column pairing distance)

#define GL_PER   (2 * LSZ - 1)
#define SQ_PER   (2 * (LSZ - 2))
#define GL_TOT   (NB * GL_PER)      // 8184
#define SQ_TOT   (NB * SQ_PER)      // 8160
#define EDGE_TOT (2 * GL_TOT + 2 * SQ_TOT)   // 32688
#define EDGE_BLOCKS ((EDGE_TOT + 255) / 256) // 128

typedef unsigned long long u64;

// Interleaved paired SoA per channel c, per (graph b, q in [0,256)):
//   g_q1[c][b*HB+q] = (x_lo, x_hi, y_lo, y_hi)
//   g_q2[c][b*HB+q] = (z_lo, z_hi, w_lo, w_hi)
// lo = node b*512+q, hi = node b*512+q+256.
// w = |x|^2, or 1e30 sentinel if channel padded OR node is BOS/global.
__device__ float4 g_q1[CC][NB * HB];
__device__ float4 g_q2[CC][NB * HB];
__device__ int    g_info[NN];   // bits 0..5: pad mask; bit 6: BOS/global

// ---- packed f32x2 helpers (each half rounds identically to scalar op) ----
__device__ __forceinline__ u64 pack2(float lo, float hi) {
    u64 r; asm("mov.b64 %0, {%1, %2};" : "=l"(r) : "f"(lo), "f"(hi)); return r;
}
__device__ __forceinline__ void unpack2(u64 v, float& lo, float& hi) {
    asm("mov.b64 {%0, %1}, %2;" : "=f"(lo), "=f"(hi) : "l"(v));
}
__device__ __forceinline__ u64 mul2(u64 a, u64 b) {
    u64 d; asm("mul.rn.f32x2 %0, %1, %2;" : "=l"(d) : "l"(a), "l"(b)); return d;
}
__device__ __forceinline__ u64 add2(u64 a, u64 b) {
    u64 d; asm("add.rn.f32x2 %0, %1, %2;" : "=l"(d) : "l"(a), "l"(b)); return d;
}
__device__ __forceinline__ u64 fma2(u64 a, u64 b, u64 c) {
    u64 d; asm("fma.rn.f32x2 %0, %1, %2, %3;" : "=l"(d) : "l"(a), "l"(b), "l"(c)); return d;
}

// ---------------------------------------------------------------------------
// Kernel 1: prep (interleaved paired SoA + masks) merged with edge lists
// ---------------------------------------------------------------------------
__global__ void __launch_bounds__(256)
prep_edges_kernel(const float* __restrict__ X,
                  const int* __restrict__ AP,
                  const int* __restrict__ S,
                  float* __restrict__ out) {
    const int tid = threadIdx.x;
    if (blockIdx.x < NB) {
        const int b = blockIdx.x;
        const int q = tid;
        float ax[2][CC], ay[2][CC], az[2][CC], aw[2][CC];
#pragma unroll
        for (int h = 0; h < 2; h++) {
            const int i = b * LSZ + h * HB + q;
            const bool bos = (S[i] == 0);
            int mask = bos ? 64 : 0;
#pragma unroll
            for (int c = 0; c < CC; c++) {
                float x = X[(i * CC + c) * 3 + 0];
                float y = X[(i * CC + c) * 3 + 1];
                float z = X[(i * CC + c) * 3 + 2];
                float sq = x * x + y * y + z * z;
                bool pad = (AP[i * CC + c] == 0);
                if (pad) mask |= (1 << c);
                ax[h][c] = x; ay[h][c] = y; az[h][c] = z;
                aw[h][c] = (pad || bos) ? 1e30f : sq;
            }
            g_info[i] = mask;
        }
#pragma unroll
        for (int c = 0; c < CC; c++) {
            g_q1[c][b * HB + q] = make_float4(ax[0][c], ax[1][c], ay[0][c], ay[1][c]);
            g_q2[c][b * HB + q] = make_float4(az[0][c], az[1][c], aw[0][c], aw[1][c]);
        }
    } else {
        const int t = (blockIdx.x - NB) * 256 + tid;
        if (t >= EDGE_TOT) return;
        int val;
        if (t < 2 * GL_TOT) {
            int r = t / GL_TOT, u = t % GL_TOT;
            int b = u / GL_PER, q = u % GL_PER;
            if (r == 0) val = (q < LSZ) ? 0 : (q - (LSZ - 1));
            else        val = (q < LSZ) ? q : 0;
            val += b * LSZ;
        } else {
            int t2 = t - 2 * GL_TOT;
            int r = t2 / SQ_TOT, u = t2 % SQ_TOT;
            int b = u / SQ_PER, q = u % SQ_PER;
            if (r == 0) val = (q < LSZ - 2) ? (q + 1) : (q - (LSZ - 2) + 2);
            else        val = (q < LSZ - 2) ? (q + 2) : (q - (LSZ - 2) + 1);
            val += b * LSZ;
        }
        out[4 * NK + t] = (float)val;
    }
}

// ---------------------------------------------------------------------------
// Kernel 2: per-row masked min-pair distance (bit-exact) + top-9 with exact
// lower-index tie-break via REDUX.MIN. One CTA per row; 128 threads; thread t
// owns columns t, t+128, t+256, t+384 (ascending for stable tie order),
// computed as two packed f32x2 column pairs (t,t+256) and (t+128,t+384).
// ---------------------------------------------------------------------------
__global__ void __launch_bounds__(128)
knn_kernel(const int* __restrict__ sec, float* __restrict__ out) {
    const int i   = blockIdx.x;
    const int b   = i >> 9;
    const int tid = threadIdx.x;
    const float INF = __int_as_float(0x7f800000);

    __shared__ u64 wOut[4 * KK];

    const int infoI = g_info[i];

    // BOS/global row: entire dist row is 1e10 -> dknn=1e10, valid=0, dst=-1.
    if (infoI & 64) {
        if (tid < KK) {
            out[0 * NK + i * KK + tid] = 1e10f;
            out[1 * NK + i * KK + tid] = (float)i;
            out[2 * NK + i * KK + tid] = -1.0f;
            out[3 * NK + i * KK + tid] = 0.0f;
        }
        return;
    }

    const int base = b * HB;
    const int li   = i & (LSZ - 1);
    const int qi   = li & (HB - 1);
    const int hi_  = li >> 8;       // which half of the pair holds row i

    // per-thread candidates in ascending column order
    float d0, d1, d2, d3;
    int   jl0 = tid, jl1 = tid + 128, jl2 = tid + 256, jl3 = tid + 384;

    if ((infoI & 63) != 63) {
        // ---------------- fast path: row has >=1 valid channel ----------------
        u64 ax2[CC], ay2[CC], az2[CC], aw2[CC];
#pragma unroll
        for (int c = 0; c < CC; c++) {
            float4 q1 = g_q1[c][base + qi];
            float4 q2 = g_q2[c][base + qi];
            float x = hi_ ? q1.y : q1.x;
            float y = hi_ ? q1.w : q1.z;
            float z = hi_ ? q2.y : q2.x;
            float w = hi_ ? q2.w : q2.z;
            ax2[c] = pack2(x, x);
            ay2[c] = pack2(y, y);
            az2[c] = pack2(z, z);
            aw2[c] = pack2(w, w);
        }
        const u64 neg2 = pack2(-2.0f, -2.0f);

#pragma unroll
        for (int p = 0; p < 2; p++) {
            const int q = tid + p * 128;
            float mlo = 3.4e38f, mhi = 3.4e38f;
#pragma unroll
            for (int d = 0; d < CC; d++) {
                ulonglong2 vA = *reinterpret_cast<const ulonglong2*>(&g_q1[d][base + q]);
                ulonglong2 vB = *reinterpret_cast<const ulonglong2*>(&g_q2[d][base + q]);
                const u64 bx2 = vA.x, by2 = vA.y, bz2 = vB.x, bw2 = vB.y;
#pragma unroll
                for (int c = 0; c < CC; c++) {
                    // BIT-EXACT chain (validated): dot = fma(ax,bx,fma(ay,by,az*bz));
                    // r = fma(-2, dot, aw+bw)
                    u64 t2 = mul2(az2[c], bz2);
                    t2 = fma2(ay2[c], by2, t2);
                    t2 = fma2(ax2[c], bx2, t2);
                    u64 s2 = add2(aw2[c], bw2);
                    u64 r2 = fma2(neg2, t2, s2);
                    float rl, rh; unpack2(r2, rl, rh);
                    mlo = fminf(mlo, rl);
                    mhi = fminf(mhi, rh);
                }
            }
            // sqrt & clamp hoisted out of the 36-way min (monotone)
            float dl = sqrtf(fmaxf(mlo, 0.0f));
            float dh = sqrtf(fmaxf(mhi, 0.0f));
            if (p == 0) { d0 = dl; d2 = dh; }   // cols tid, tid+256
            else        { d1 = dl; d3 = dh; }   // cols tid+128, tid+384
        }
    } else {
        // ---------------- cold fallback: row has no valid channel -------------
        // dist_j = 1e10 (BOS col) or 1e10 + sqrt(min_all d2); valid=0 always.
        float Ax[CC], Ay[CC], Az[CC], Asq[CC];
#pragma unroll
        for (int c = 0; c < CC; c++) {
            float4 q1 = g_q1[c][base + qi];
            float4 q2 = g_q2[c][base + qi];
            float x = hi_ ? q1.y : q1.x;
            float y = hi_ ? q1.w : q1.z;
            float z = hi_ ? q2.y : q2.x;
            Ax[c] = x; Ay[c] = y; Az[c] = z;
            Asq[c] = x * x + y * y + z * z;
        }
        float dv[4];
#pragma unroll
        for (int t = 0; t < 4; t++) {
            const int jl = tid + t * 128;          // ascending, matches jl0..jl3
            const int q  = jl & (HB - 1);
            const int hh = jl >> 8;
            const int j  = (b << 9) + jl;
            float dist;
            if (g_info[j] & 64) {
                dist = 1e10f;
            } else {
                float m = 3.4e38f;
#pragma unroll
                for (int d = 0; d < CC; d++) {
                    float4 q1 = g_q1[d][base + q];
                    float4 q2 = g_q2[d][base + q];
                    float bx = hh ? q1.y : q1.x;
                    float by = hh ? q1.w : q1.z;
                    float bz = hh ? q2.y : q2.x;
                    float bsq = bx * bx + by * by + bz * bz;
#pragma unroll
                    for (int c = 0; c < CC; c++) {
                        float dot = fmaf(Ax[c], bx, fmaf(Ay[c], by, Az[c] * bz));
                        float r = fmaf(-2.0f, dot, Asq[c] + bsq);
                        m = fminf(m, r);
                    }
                }
                dist = 1e10f + sqrtf(fmaxf(m, 0.0f));
            }
            dv[t] = dist;
        }
        d0 = dv[0]; d1 = dv[1]; d2 = dv[2]; d3 = dv[3];
    }

    // stable sort of 4 (dist, jl) candidates (strict >; equal keys never cross,
    // so ties stay in ascending-jl order)
#define CSWAP(da, db, ja, jb) { \
    if (da > db) { float tf = da; da = db; db = tf; int ti = ja; ja = jb; jb = ti; } }
    CSWAP(d0, d1, jl0, jl1) CSWAP(d2, d3, jl2, jl3)
    CSWAP(d0, d2, jl0, jl2) CSWAP(d1, d3, jl1, jl3)
    CSWAP(d1, d2, jl1, jl2)
#undef CSWAP

    // per-warp: 9 rounds of REDUX.MIN warp-min (dist bits are order-isomorphic
    // as u32 since dist >= 0) with exact lower-index tie-break.
    const int wid = tid >> 5;
    for (int r = 0; r < KK; r++) {
        unsigned db = __float_as_uint(d0);
        unsigned m  = __reduce_min_sync(0xFFFFFFFFu, db);
        unsigned cj = __reduce_min_sync(0xFFFFFFFFu,
                                        (db == m) ? (unsigned)jl0 : 0xFFFFFFFFu);
        if (db == m && (unsigned)jl0 == cj) {     // unique owner (jl unique)
            wOut[wid * KK + r] = ((u64)m << 32) | cj;
            // pop head (shift register; no dynamic indexing)
            d0 = d1; jl0 = jl1;
            d1 = d2; jl1 = jl2;
            d2 = d3; jl2 = jl3;
            d3 = INF;
        }
    }
    __syncthreads();

    // parallel rank-merge of 4 sorted 9-lists; ranks < 9 write outputs directly.
    // u64 keys carry (dist_bits, jl) so cross-warp ties also rank by lower jl.
    if (tid < 4 * KK) {
        const u64 key = wOut[tid];
        const int myw = tid / KK;
        int rank = tid - myw * KK;
#pragma unroll
        for (int w = 0; w < 4; w++) {
            if (w == myw) continue;
#pragma unroll
            for (int rr = 0; rr < KK; rr++)
                rank += (wOut[w * KK + rr] < key);
        }
        if (rank < KK) {
            float dd = __uint_as_float((unsigned)(key >> 32));
            int   jl = (int)(key & 0xFFFFFFFFu);
            int  dst = (b << 9) + jl;
            bool valid = (dd < 1e10f) && (sec[i] == sec[dst]);
            out[0 * NK + i * KK + rank] = dd;
            out[1 * NK + i * KK + rank] = (float)i;
            out[2 * NK + i * KK + rank] = valid ? (float)dst : -1.0f;
            out[3 * NK + i * KK + rank] = valid ? 1.0f : 0.0f;
        }
    }
}

// ---------------------------------------------------------------------------
extern "C" void kernel_launch(void* const* d_in, const int* in_sizes, int n_in,
                              void* d_out, int out_size) {
    const float* X   = (const float*)d_in[0];
    const int*   AP  = (const int*)d_in[1];
    const int*   S   = (const int*)d_in[2];
    const int*   sec = (const int*)d_in[3];
    float* out = (float*)d_out;

    prep_edges_kernel<<<NB + EDGE_BLOCKS, 256>>>(X, AP, S, out);
    knn_kernel<<<NN, 128>>>(sec, out);
}